// round 1
// baseline (speedup 1.0000x reference)
#include <cuda_runtime.h>
#include <math.h>

// ---- problem constants ----
#define NBATCH 4
#define NATOMS 600
#define NBINS  64
#define NPAIR_PER_B (NATOMS * NATOMS)   // 360000
#define TOTAL_P (NBATCH * NPAIR_PER_B)  // 1440000

// box / cutoff constants (float32, matching the jnp reference)
#define BOX_L      20.0f
#define HALF_L     10.0f
#define BIN_W      (7.5f / 64.0f)        // BINS spacing = 0.1171875 (exact)
#define CUT_ADJ    7.734375f             // 7.5 + 2*BIN_W (exact)
#define GW         (7.5f / 63.0f)        // Gaussian offset spacing == width
#define GCOEFF     (-0.5f / (GW * GW))
#define QRATIO     0.3678794411714423f   // exp(2*GCOEFF*GW^2) = e^-1 (exact)

// global accumulator (no cudaMalloc allowed)
__device__ float g_count[NBINS];

__global__ void rdf_zero_kernel() {
    if (threadIdx.x < NBINS) g_count[threadIdx.x] = 0.0f;
}

__global__ void __launch_bounds__(256) rdf_accum_kernel(const float* __restrict__ xyz) {
    __shared__ float sbins[NBINS];
    if (threadIdx.x < NBINS) sbins[threadIdx.x] = 0.0f;
    __syncthreads();

    const float cut2 = CUT_ADJ * CUT_ADJ;
    const float w = GW;
    const float c = GCOEFF;
    const float inv_w = 1.0f / GW;

    const int stride = gridDim.x * blockDim.x;
    for (int p = blockIdx.x * blockDim.x + threadIdx.x; p < TOTAL_P; p += stride) {
        int b = p / NPAIR_PER_B;
        int r = p - b * NPAIR_PER_B;
        int i = r / NATOMS;
        int j = r - i * NATOMS;
        if (j <= i) continue;   // unordered pairs: count scales by 1/2 exactly,
                                // rdf is normalization-invariant

        const float* __restrict__ pi = xyz + (b * NATOMS + i) * 3;
        const float* __restrict__ pj = xyz + (b * NATOMS + j) * 3;

        float dx = __ldg(pj + 0) - __ldg(pi + 0);
        float dy = __ldg(pj + 1) - __ldg(pi + 1);
        float dz = __ldg(pj + 2) - __ldg(pi + 2);
        // minimum-image wrap (positions in [0,L) so one wrap suffices)
        if (dx >= HALF_L) dx -= BOX_L; else if (dx < -HALF_L) dx += BOX_L;
        if (dy >= HALF_L) dy -= BOX_L; else if (dy < -HALF_L) dy += BOX_L;
        if (dz >= HALF_L) dz -= BOX_L; else if (dz < -HALF_L) dz += BOX_L;

        float ds = dx * dx + dy * dy + dz * dz;
        if (ds >= cut2 || ds == 0.0f) continue;

        float d = sqrtf(ds);

        // 17-bin window around the nearest Gaussian offset:
        // beyond +-8 widths the term is exp(-32) ~ 1e-14 relative -> negligible
        int kc = (int)(d * inv_w + 0.5f);
        int k0 = kc - 8; if (k0 < 0) k0 = 0;
        int k1 = kc + 8; if (k1 > NBINS - 1) k1 = NBINS - 1;

        // exp recurrence: e_{k+1} = e_k * t_k ; t_{k+1} = t_k * q, q = e^-1
        float u = d - (float)k0 * w;
        float e = __expf(c * u * u);
        float t = __expf(c * (w * w - 2.0f * u * w));
        for (int k = k0; k <= k1; ++k) {
            atomicAdd(&sbins[k], e);
            e *= t;
            t *= QRATIO;
        }
    }

    __syncthreads();
    if (threadIdx.x < NBINS) {
        float v = sbins[threadIdx.x];
        if (v != 0.0f) atomicAdd(&g_count[threadIdx.x], v);
    }
}

__global__ void rdf_finalize_kernel(float* __restrict__ out, int out_size) {
    __shared__ float cnt[NBINS];
    __shared__ float total_s;
    int t = threadIdx.x;
    if (t < NBINS) cnt[t] = g_count[t];
    __syncthreads();
    if (t == 0) {
        float s = 0.0f;
        for (int k = 0; k < NBINS; ++k) s += cnt[k];
        total_s = s;
    }
    __syncthreads();

    const float pi43 = 4.0f * 3.14159265358979f / 3.0f;
    const float num = (2.0f * CUT_ADJ) * (2.0f * CUT_ADJ) * (2.0f * CUT_ADJ);

    if (out_size >= NBINS + 1 + NBINS) {
        // layout: BINS[65] then rdf[64]
        if (t < NBINS + 1) out[t] = (float)t * BIN_W;
        if (t < NBINS) {
            float b0 = (float)t * BIN_W;
            float b1 = (float)(t + 1) * BIN_W;
            float vol = pi43 * (b1 * b1 * b1 - b0 * b0 * b0);
            float cn = cnt[t] / total_s;
            out[NBINS + 1 + t] = cn * num / (2.0f * vol);
        }
    } else {
        // rdf only
        if (t < NBINS && t < out_size) {
            float b0 = (float)t * BIN_W;
            float b1 = (float)(t + 1) * BIN_W;
            float vol = pi43 * (b1 * b1 * b1 - b0 * b0 * b0);
            float cn = cnt[t] / total_s;
            out[t] = cn * num / (2.0f * vol);
        }
    }
}

extern "C" void kernel_launch(void* const* d_in, const int* in_sizes, int n_in,
                              void* d_out, int out_size) {
    const float* xyz = (const float*)d_in[0];
    float* out = (float*)d_out;

    rdf_zero_kernel<<<1, 64>>>();
    rdf_accum_kernel<<<592, 256>>>(xyz);
    rdf_finalize_kernel<<<1, 128>>>(out, out_size);
}